// round 1
// baseline (speedup 1.0000x reference)
#include <cuda_runtime.h>
#include <cuda_bf16.h>
#include <math.h>

// ---------------------------------------------------------------------------
// Sparse UNet block:
//   stage1: BN+ReLU(feat)   -> subconv 3^3 (27 taps, 32->32)  -> skip (cat[:,0:32])
//   stage2: BN+ReLU(skip)   -> conv 2^3 (8 taps, 32->64)      -> xc  [M,64]
//   stage3: BN+ReLU(xc)     -> subconv 3^3 (27 taps, 64->64)  -> xc2 [M,64]
//   stage4: BN+ReLU(xc2)    -> deconv (per-row tap, 64->32)   -> cat[:,32:64]
//   stage5: BN+ReLU(cat)    -> subconv 3^3 (27 taps, 64->32)  -> out [N,32]
// BN is training-mode batch stats, folded into scale/shift applied at gather.
// Sentinel neighbor index == number of real rows -> contributes zero.
// ---------------------------------------------------------------------------

#define NMAX 200000
#define EPSF 1e-4f

__device__ float g_cat[NMAX * 64];   // skip | upsampled
__device__ float g_xc [NMAX * 64];   // coarse feats after down conv
__device__ float g_xc2[NMAX * 64];   // coarse feats after subconv2
__device__ double g_sums[128];       // per-channel sum / sumsq
__device__ float g_scale[64];
__device__ float g_shift[64];

// ---------------------------------------------------------------------------
__global__ void zero_sums_kernel() {
    g_sums[threadIdx.x] = 0.0;
}

// per-channel sum & sumsq over nrows rows; C channels, row stride ld
template <int C>
__global__ void stats_kernel(const float* __restrict__ x, int nrows, int ld) {
    const int rpb = 256 / C;                       // rows handled per block pass
    int c  = threadIdx.x % C;
    int r0 = blockIdx.x * rpb + threadIdx.x / C;
    int rs = gridDim.x * rpb;
    double s = 0.0, s2 = 0.0;
    for (int r = r0; r < nrows; r += rs) {
        float v = x[(size_t)r * ld + c];
        s  += (double)v;
        s2 += (double)v * (double)v;
    }
    atomicAdd(&g_sums[c], s);
    atomicAdd(&g_sums[64 + c], s2);
}

__global__ void finalize_kernel(const float* __restrict__ g,
                                const float* __restrict__ b,
                                int C, float inv_n) {
    int c = threadIdx.x;
    if (c >= C) return;
    float mu  = (float)(g_sums[c] * inv_n);
    float var = (float)(g_sums[64 + c] * inv_n) - mu * mu;
    float inv = rsqrtf(var + EPSF);
    float sc  = g[c] * inv;
    g_scale[c] = sc;
    g_shift[c] = b[c] - mu * sc;
}

// ---------------------------------------------------------------------------
// Fused BN+ReLU gather + K-tap GEMM accumulate.
// One thread per output row; W tap staged in shared memory.
template <int CIN, int COUT, int KT>
__launch_bounds__(128)
__global__ void conv_kernel(const float* __restrict__ fin, int ld_in,
                            const int* __restrict__ nbr, int nrows, int sentinel,
                            const float* __restrict__ W,
                            float* __restrict__ out, int ld_out) {
    __shared__ float Wsm[CIN * COUT];
    __shared__ float ssm[CIN];
    __shared__ float bsm[CIN];

    if (threadIdx.x < CIN) {
        ssm[threadIdx.x] = g_scale[threadIdx.x];
        bsm[threadIdx.x] = g_shift[threadIdx.x];
    }

    int row = blockIdx.x * blockDim.x + threadIdx.x;

    float acc[COUT];
#pragma unroll
    for (int j = 0; j < COUT; j++) acc[j] = 0.f;

    for (int k = 0; k < KT; k++) {
        __syncthreads();
        for (int t = threadIdx.x; t < CIN * COUT / 4; t += blockDim.x)
            ((float4*)Wsm)[t] = ((const float4*)(W + (size_t)k * CIN * COUT))[t];
        __syncthreads();

        if (row < nrows) {
            int idx = nbr[(size_t)k * nrows + row];
            if (idx < sentinel) {
                const float4* fr = (const float4*)(fin + (size_t)idx * ld_in);
#pragma unroll
                for (int c4 = 0; c4 < CIN / 4; c4++) {
                    float4 fv = __ldg(&fr[c4]);
                    float f[4];
                    f[0] = fmaxf(fv.x * ssm[4 * c4 + 0] + bsm[4 * c4 + 0], 0.f);
                    f[1] = fmaxf(fv.y * ssm[4 * c4 + 1] + bsm[4 * c4 + 1], 0.f);
                    f[2] = fmaxf(fv.z * ssm[4 * c4 + 2] + bsm[4 * c4 + 2], 0.f);
                    f[3] = fmaxf(fv.w * ssm[4 * c4 + 3] + bsm[4 * c4 + 3], 0.f);
#pragma unroll
                    for (int cc = 0; cc < 4; cc++) {
                        const float* wr = &Wsm[(4 * c4 + cc) * COUT];
#pragma unroll
                        for (int j = 0; j < COUT; j += 4) {
                            float4 wv = *(const float4*)(wr + j);
                            acc[j + 0] += f[cc] * wv.x;
                            acc[j + 1] += f[cc] * wv.y;
                            acc[j + 2] += f[cc] * wv.z;
                            acc[j + 3] += f[cc] * wv.w;
                        }
                    }
                }
            }
        }
    }

    if (row < nrows) {
#pragma unroll
        for (int j = 0; j < COUT; j += 4) {
            float4 o = make_float4(acc[j], acc[j + 1], acc[j + 2], acc[j + 3]);
            *(float4*)(out + (size_t)row * ld_out + j) = o;
        }
    }
}

// ---------------------------------------------------------------------------
// Deconv: each fine row reads its unique coarse parent (BN+ReLU applied) and
// multiplies by the per-row kernel tap W[up_k]. Writes cat[:,32:64].
__launch_bounds__(128)
__global__ void deconv_kernel(const float* __restrict__ xc2,
                              const int* __restrict__ up_cidx,
                              const int* __restrict__ up_k,
                              const float* __restrict__ Wup,
                              float* __restrict__ out, int nrows) {
    __shared__ float ssm[64];
    __shared__ float bsm[64];
    if (threadIdx.x < 64) {
        ssm[threadIdx.x] = g_scale[threadIdx.x];
        bsm[threadIdx.x] = g_shift[threadIdx.x];
    }
    __syncthreads();

    int row = blockIdx.x * blockDim.x + threadIdx.x;
    if (row >= nrows) return;

    int ci = up_cidx[row];
    int kk = up_k[row];
    const float* W = Wup + (size_t)kk * 64 * 32;

    float acc[32];
#pragma unroll
    for (int j = 0; j < 32; j++) acc[j] = 0.f;

    const float4* fr = (const float4*)(xc2 + (size_t)ci * 64);
#pragma unroll
    for (int c4 = 0; c4 < 16; c4++) {
        float4 fv = __ldg(&fr[c4]);
        float f[4];
        f[0] = fmaxf(fv.x * ssm[4 * c4 + 0] + bsm[4 * c4 + 0], 0.f);
        f[1] = fmaxf(fv.y * ssm[4 * c4 + 1] + bsm[4 * c4 + 1], 0.f);
        f[2] = fmaxf(fv.z * ssm[4 * c4 + 2] + bsm[4 * c4 + 2], 0.f);
        f[3] = fmaxf(fv.w * ssm[4 * c4 + 3] + bsm[4 * c4 + 3], 0.f);
#pragma unroll
        for (int cc = 0; cc < 4; cc++) {
            const float4* wr = (const float4*)(W + (size_t)(4 * c4 + cc) * 32);
#pragma unroll
            for (int j4 = 0; j4 < 8; j4++) {
                float4 wv = __ldg(&wr[j4]);
                acc[4 * j4 + 0] += f[cc] * wv.x;
                acc[4 * j4 + 1] += f[cc] * wv.y;
                acc[4 * j4 + 2] += f[cc] * wv.z;
                acc[4 * j4 + 3] += f[cc] * wv.w;
            }
        }
    }

    float* op = out + (size_t)row * 64 + 32;
#pragma unroll
    for (int j = 0; j < 32; j += 4)
        *(float4*)(op + j) = make_float4(acc[j], acc[j + 1], acc[j + 2], acc[j + 3]);
}

// ---------------------------------------------------------------------------
extern "C" void kernel_launch(void* const* d_in, const int* in_sizes, int n_in,
                              void* d_out, int out_size) {
    const float* feat    = (const float*)d_in[0];
    const float* w_sub1  = (const float*)d_in[1];
    const float* w_down  = (const float*)d_in[2];
    const float* w_sub2  = (const float*)d_in[3];
    const float* w_up    = (const float*)d_in[4];
    const float* w_sub3  = (const float*)d_in[5];
    const float* g1 = (const float*)d_in[6];  const float* b1 = (const float*)d_in[7];
    const float* g2 = (const float*)d_in[8];  const float* b2 = (const float*)d_in[9];
    const float* g3 = (const float*)d_in[10]; const float* b3 = (const float*)d_in[11];
    const float* g4 = (const float*)d_in[12]; const float* b4 = (const float*)d_in[13];
    const float* g5 = (const float*)d_in[14]; const float* b5 = (const float*)d_in[15];
    const int* nbr_fine   = (const int*)d_in[16];
    const int* nbr_coarse = (const int*)d_in[17];
    const int* down_idx   = (const int*)d_in[18];
    const int* up_cidx    = (const int*)d_in[19];
    const int* up_k       = (const int*)d_in[20];

    const int N = in_sizes[0] / 32;
    const int M = in_sizes[18] / 8;

    float* cat_ptr; float* xc_ptr; float* xc2_ptr;
    cudaGetSymbolAddress((void**)&cat_ptr, g_cat);
    cudaGetSymbolAddress((void**)&xc_ptr,  g_xc);
    cudaGetSymbolAddress((void**)&xc2_ptr, g_xc2);

    const int TB = 128;
    dim3 gridN((N + TB - 1) / TB);
    dim3 gridM((M + TB - 1) / TB);
    const int SG = 512;  // stats grid

    // ---- stage 1: BN(feat) -> subconv1 (32->32) into cat[:,0:32]
    zero_sums_kernel<<<1, 128>>>();
    stats_kernel<32><<<SG, 256>>>(feat, N, 32);
    finalize_kernel<<<1, 64>>>(g1, b1, 32, 1.0f / N);
    conv_kernel<32, 32, 27><<<gridN, TB>>>(feat, 32, nbr_fine, N, N,
                                           w_sub1, cat_ptr, 64);

    // ---- stage 2: BN(skip) -> down conv (32->64) into xc
    zero_sums_kernel<<<1, 128>>>();
    stats_kernel<32><<<SG, 256>>>(cat_ptr, N, 64);
    finalize_kernel<<<1, 64>>>(g2, b2, 32, 1.0f / N);
    conv_kernel<32, 64, 8><<<gridM, TB>>>(cat_ptr, 64, down_idx, M, N,
                                          w_down, xc_ptr, 64);

    // ---- stage 3: BN(xc) -> subconv2 (64->64) into xc2
    zero_sums_kernel<<<1, 128>>>();
    stats_kernel<64><<<SG, 256>>>(xc_ptr, M, 64);
    finalize_kernel<<<1, 64>>>(g3, b3, 64, 1.0f / M);
    conv_kernel<64, 64, 27><<<gridM, TB>>>(xc_ptr, 64, nbr_coarse, M, M,
                                           w_sub2, xc2_ptr, 64);

    // ---- stage 4: BN(xc2) -> deconv (64->32) into cat[:,32:64]
    zero_sums_kernel<<<1, 128>>>();
    stats_kernel<64><<<SG, 256>>>(xc2_ptr, M, 64);
    finalize_kernel<<<1, 64>>>(g4, b4, 64, 1.0f / M);
    deconv_kernel<<<gridN, TB>>>(xc2_ptr, up_cidx, up_k, w_up, cat_ptr, N);

    // ---- stage 5: BN(cat) -> subconv3 (64->32) into out
    zero_sums_kernel<<<1, 128>>>();
    stats_kernel<64><<<SG, 256>>>(cat_ptr, N, 64);
    finalize_kernel<<<1, 64>>>(g5, b5, 64, 1.0f / N);
    conv_kernel<64, 32, 27><<<gridN, TB>>>(cat_ptr, 64, nbr_fine, N, N,
                                           w_sub3, (float*)d_out, 32);
}

// round 3
// speedup vs baseline: 2.8973x; 2.8973x over previous
#include <cuda_runtime.h>
#include <math.h>

// ---------------------------------------------------------------------------
// Sparse UNet block via tap-compacted dense gather-GEMMs.
//   For each conv stage: compact valid (out_row, in_row) pairs per kernel tap,
//   then run a register-tiled GEMM per tap-segment with W staged in smem and
//   red.v4 scatter-accumulate into the output.
// BN (training-mode batch stats) folded into scale/shift applied at gather.
// ---------------------------------------------------------------------------

#define NMAX 200000
#define EPSF 1e-4f
#define TPAIR 64
#define GEMM_GRID 4096

__device__ float g_cat[NMAX * 64];     // skip | upsampled (fine)
__device__ float g_xc [NMAX * 64];     // coarse after down conv
__device__ float g_xc2[NMAX * 64];     // coarse after subconv2
__device__ int2  g_pairs[27 * NMAX];   // per-tap pair segments (row, idx)
__device__ int   g_cnt[32];
__device__ int   g_tilebase[32];
__device__ double g_sums[128];
__device__ float g_scale[64];
__device__ float g_shift[64];

// ---------------------------------------------------------------------------
__global__ void prep_kernel() {
    int t = threadIdx.x;
    g_sums[t] = 0.0;
    if (t < 32) g_cnt[t] = 0;
}

// per-channel sum & sumsq over nrows rows; C channels, row stride ld
template <int C>
__global__ void stats_kernel(const float* __restrict__ x, int nrows, int ld) {
    const int rpb = 256 / C;
    int c  = threadIdx.x % C;
    int r0 = blockIdx.x * rpb + threadIdx.x / C;
    int rs = gridDim.x * rpb;
    double s = 0.0, s2 = 0.0;
    for (int r = r0; r < nrows; r += rs) {
        float v = x[(size_t)r * ld + c];
        s  += (double)v;
        s2 += (double)v * (double)v;
    }
    atomicAdd(&g_sums[c], s);
    atomicAdd(&g_sums[64 + c], s2);
}

__global__ void finalize_kernel(const float* __restrict__ g,
                                const float* __restrict__ b,
                                int C, float inv_n) {
    int c = threadIdx.x;
    if (c >= C) return;
    float mu  = (float)(g_sums[c] * inv_n);
    float var = (float)(g_sums[64 + c] * inv_n) - mu * mu;
    float inv = rsqrtf(var + EPSF);
    float sc  = g[c] * inv;
    g_scale[c] = sc;
    g_shift[c] = b[c] - mu * sc;
}

// ---------------------------------------------------------------------------
// Compaction: pairs of (out_row, in_row) per tap, segment k at g_pairs[k*NMAX..]
__global__ void compact_kernel(const int* __restrict__ nbr, int nrows, int sentinel) {
    int k = blockIdx.y;
    int r = blockIdx.x * 256 + threadIdx.x;
    if (r >= nrows) return;
    int idx = nbr[(size_t)k * nrows + r];
    if (idx < sentinel) {
        int p = atomicAdd(&g_cnt[k], 1);     // warp-uniform addr -> REDUX aggregate
        g_pairs[k * NMAX + p] = make_int2(r, idx);
    }
}

// Deconv as tap lists: fine row r belongs to tap up_k[r], gathers up_cidx[r].
__global__ void compact_deconv_kernel(const int* __restrict__ up_cidx,
                                      const int* __restrict__ up_k, int nrows) {
    int k = blockIdx.y;
    int r = blockIdx.x * 256 + threadIdx.x;
    if (r >= nrows) return;
    if (up_k[r] == k) {
        int p = atomicAdd(&g_cnt[k], 1);
        g_pairs[k * NMAX + p] = make_int2(r, up_cidx[r]);
    }
}

__global__ void plan_kernel(int K) {
    if (threadIdx.x == 0) {
        int s = 0;
        for (int k = 0; k < K; k++) {
            g_tilebase[k] = s;
            s += (g_cnt[k] + TPAIR - 1) / TPAIR;
        }
        g_tilebase[K] = s;
    }
}

// ---------------------------------------------------------------------------
__device__ __forceinline__ void red_add_v4(float* a, float x, float y, float z, float w) {
    asm volatile("red.global.add.v4.f32 [%0], {%1,%2,%3,%4};"
                 :: "l"(a), "f"(x), "f"(y), "f"(z), "f"(w) : "memory");
}

// Tap-segmented gather-GEMM. Block = 128 threads handles TPAIR=64 pairs/tile,
// striding over all live tiles. Thread tile = 4 pairs x (COUT/8) couts.
template <int CIN, int COUT>
__launch_bounds__(128)
__global__ void tapgemm_kernel(const float* __restrict__ fin, int ld_in,
                               const float* __restrict__ W,
                               float* __restrict__ out, int ld_out, int K) {
    constexpr int CP = CIN + 2;     // padded A stride: conflict-free scalar reads
    constexpr int CT = COUT / 8;    // couts per thread
    constexpr int C4 = CIN / 4;

    __shared__ __align__(16) float Wsm[CIN * COUT];
    __shared__ float Asm[TPAIR * CP];
    __shared__ int   rowsm[TPAIR];
    __shared__ int   idxsm[TPAIR];
    __shared__ float ssm[CIN], bsm[CIN];
    __shared__ int   tbsm[32], cntsm[32];

    int tid = threadIdx.x;
    if (tid < CIN) { ssm[tid] = g_scale[tid]; bsm[tid] = g_shift[tid]; }
    if (tid <= K)  { tbsm[tid] = g_tilebase[tid]; }
    if (tid <  K)  { cntsm[tid] = g_cnt[tid]; }
    __syncthreads();

    int total = tbsm[K];
    int tx = tid & 7;        // cout group
    int ty = tid >> 3;       // pair group (0..15)
    int pa = ty * 4;

    for (int t = blockIdx.x; t < total; t += gridDim.x) {
        int k = 0;
        while (tbsm[k + 1] <= t) k++;
        int t0 = (t - tbsm[k]) * TPAIR;
        int np = min(TPAIR, cntsm[k] - t0);

        // stage W tap + pair chunk
        {
            const float4* Wg = (const float4*)(W + (size_t)k * CIN * COUT);
            #pragma unroll
            for (int i = tid; i < CIN * COUT / 4; i += 128)
                ((float4*)Wsm)[i] = __ldg(&Wg[i]);
            if (tid < TPAIR) {
                if (tid < np) {
                    int2 pr = g_pairs[k * NMAX + t0 + tid];
                    rowsm[tid] = pr.x; idxsm[tid] = pr.y;
                } else { rowsm[tid] = -1; idxsm[tid] = 0; }
            }
        }
        __syncthreads();

        // gather + BN + ReLU into Asm (transposed-read-friendly padded layout)
        for (int i = tid; i < TPAIR * C4; i += 128) {
            int p  = i / C4;
            int c4 = i % C4;
            float4 v = __ldg((const float4*)(fin + (size_t)idxsm[p] * ld_in) + c4);
            int c = c4 * 4;
            float* ap = &Asm[p * CP + c];
            ap[0] = fmaxf(fmaf(v.x, ssm[c + 0], bsm[c + 0]), 0.f);
            ap[1] = fmaxf(fmaf(v.y, ssm[c + 1], bsm[c + 1]), 0.f);
            ap[2] = fmaxf(fmaf(v.z, ssm[c + 2], bsm[c + 2]), 0.f);
            ap[3] = fmaxf(fmaf(v.w, ssm[c + 3], bsm[c + 3]), 0.f);
        }
        __syncthreads();

        // register-tiled GEMM: 4 pairs x CT couts per thread
        float acc[4][CT];
        #pragma unroll
        for (int i = 0; i < 4; i++)
            #pragma unroll
            for (int j = 0; j < CT; j++) acc[i][j] = 0.f;

        const float* a0p = &Asm[pa * CP];
        #pragma unroll 16
        for (int c = 0; c < CIN; c++) {
            float a0 = a0p[c];
            float a1 = a0p[CP + c];
            float a2 = a0p[2 * CP + c];
            float a3 = a0p[3 * CP + c];
            const float* wr = &Wsm[c * COUT + tx * CT];
            #pragma unroll
            for (int j4 = 0; j4 < CT / 4; j4++) {
                float4 w4 = *(const float4*)(wr + 4 * j4);
                acc[0][4*j4+0] += a0 * w4.x; acc[0][4*j4+1] += a0 * w4.y;
                acc[0][4*j4+2] += a0 * w4.z; acc[0][4*j4+3] += a0 * w4.w;
                acc[1][4*j4+0] += a1 * w4.x; acc[1][4*j4+1] += a1 * w4.y;
                acc[1][4*j4+2] += a1 * w4.z; acc[1][4*j4+3] += a1 * w4.w;
                acc[2][4*j4+0] += a2 * w4.x; acc[2][4*j4+1] += a2 * w4.y;
                acc[2][4*j4+2] += a2 * w4.z; acc[2][4*j4+3] += a2 * w4.w;
                acc[3][4*j4+0] += a3 * w4.x; acc[3][4*j4+1] += a3 * w4.y;
                acc[3][4*j4+2] += a3 * w4.z; acc[3][4*j4+3] += a3 * w4.w;
            }
        }

        // scatter-accumulate
        #pragma unroll
        for (int i = 0; i < 4; i++) {
            int r = rowsm[pa + i];
            if (r >= 0) {
                float* op = out + (size_t)r * ld_out + tx * CT;
                #pragma unroll
                for (int j4 = 0; j4 < CT / 4; j4++)
                    red_add_v4(op + 4 * j4, acc[i][4*j4], acc[i][4*j4+1],
                               acc[i][4*j4+2], acc[i][4*j4+3]);
            }
        }
        __syncthreads();
    }
}

// ---------------------------------------------------------------------------
extern "C" void kernel_launch(void* const* d_in, const int* in_sizes, int n_in,
                              void* d_out, int out_size) {
    const float* feat    = (const float*)d_in[0];
    const float* w_sub1  = (const float*)d_in[1];
    const float* w_down  = (const float*)d_in[2];
    const float* w_sub2  = (const float*)d_in[3];
    const float* w_up    = (const float*)d_in[4];
    const float* w_sub3  = (const float*)d_in[5];
    const float* g1 = (const float*)d_in[6];  const float* b1 = (const float*)d_in[7];
    const float* g2 = (const float*)d_in[8];  const float* b2 = (const float*)d_in[9];
    const float* g3 = (const float*)d_in[10]; const float* b3 = (const float*)d_in[11];
    const float* g4 = (const float*)d_in[12]; const float* b4 = (const float*)d_in[13];
    const float* g5 = (const float*)d_in[14]; const float* b5 = (const float*)d_in[15];
    const int* nbr_fine   = (const int*)d_in[16];
    const int* nbr_coarse = (const int*)d_in[17];
    const int* down_idx   = (const int*)d_in[18];
    const int* up_cidx    = (const int*)d_in[19];
    const int* up_k       = (const int*)d_in[20];

    const int N = in_sizes[0] / 32;
    const int M = in_sizes[18] / 8;

    float* cat_ptr; float* xc_ptr; float* xc2_ptr;
    cudaGetSymbolAddress((void**)&cat_ptr, g_cat);
    cudaGetSymbolAddress((void**)&xc_ptr,  g_xc);
    cudaGetSymbolAddress((void**)&xc2_ptr, g_xc2);

    // zero all accumulation targets up front
    cudaMemsetAsync(cat_ptr, 0, (size_t)N * 64 * sizeof(float));
    cudaMemsetAsync(xc_ptr,  0, (size_t)M * 64 * sizeof(float));
    cudaMemsetAsync(xc2_ptr, 0, (size_t)M * 64 * sizeof(float));
    cudaMemsetAsync(d_out,   0, (size_t)out_size * sizeof(float));

    dim3 cgN((N + 255) / 256, 27);
    dim3 cgN8((N + 255) / 256, 8);
    dim3 cgM((M + 255) / 256, 27);
    dim3 cgM8((M + 255) / 256, 8);
    const int SG = 512;

    // ---- stage 1: BN(feat) -> subconv1 (32->32, fine) into cat[:,0:32]
    prep_kernel<<<1, 128>>>();
    stats_kernel<32><<<SG, 256>>>(feat, N, 32);
    finalize_kernel<<<1, 64>>>(g1, b1, 32, 1.0f / N);
    compact_kernel<<<cgN, 256>>>(nbr_fine, N, N);
    plan_kernel<<<1, 32>>>(27);
    tapgemm_kernel<32, 32><<<GEMM_GRID, 128>>>(feat, 32, w_sub1, cat_ptr, 64, 27);

    // ---- stage 2: BN(skip) -> down conv (32->64) into xc
    prep_kernel<<<1, 128>>>();
    stats_kernel<32><<<SG, 256>>>(cat_ptr, N, 64);
    finalize_kernel<<<1, 64>>>(g2, b2, 32, 1.0f / N);
    compact_kernel<<<cgM8, 256>>>(down_idx, M, N);
    plan_kernel<<<1, 32>>>(8);
    tapgemm_kernel<32, 64><<<GEMM_GRID, 128>>>(cat_ptr, 64, w_down, xc_ptr, 64, 8);

    // ---- stage 3: BN(xc) -> subconv2 (64->64, coarse) into xc2
    prep_kernel<<<1, 128>>>();
    stats_kernel<64><<<SG, 256>>>(xc_ptr, M, 64);
    finalize_kernel<<<1, 64>>>(g3, b3, 64, 1.0f / M);
    compact_kernel<<<cgM, 256>>>(nbr_coarse, M, M);
    plan_kernel<<<1, 32>>>(27);
    tapgemm_kernel<64, 64><<<GEMM_GRID, 128>>>(xc_ptr, 64, w_sub2, xc2_ptr, 64, 27);

    // ---- stage 4: BN(xc2) -> deconv (64->32) into cat[:,32:64]
    prep_kernel<<<1, 128>>>();
    stats_kernel<64><<<SG, 256>>>(xc2_ptr, M, 64);
    finalize_kernel<<<1, 64>>>(g4, b4, 64, 1.0f / M);
    compact_deconv_kernel<<<cgN8, 256>>>(up_cidx, up_k, N);
    plan_kernel<<<1, 32>>>(8);
    tapgemm_kernel<64, 32><<<GEMM_GRID, 128>>>(xc2_ptr, 64, w_up, cat_ptr + 32, 64, 8);

    // ---- stage 5: BN(cat) -> subconv3 (64->32, fine) into out
    prep_kernel<<<1, 128>>>();
    stats_kernel<64><<<SG, 256>>>(cat_ptr, N, 64);
    finalize_kernel<<<1, 64>>>(g5, b5, 64, 1.0f / N);
    compact_kernel<<<cgN, 256>>>(nbr_fine, N, N);
    plan_kernel<<<1, 32>>>(27);
    tapgemm_kernel<64, 32><<<GEMM_GRID, 128>>>(cat_ptr, 64, w_sub3, (float*)d_out, 32, 27);
}

// round 4
// speedup vs baseline: 3.1293x; 1.0801x over previous
#include <cuda_runtime.h>
#include <math.h>

// ---------------------------------------------------------------------------
// Sparse UNet block via tap-compacted dense gather-GEMMs (f32x2-packed FFMA).
//  - All 70 tap segments (fine27 / coarse27 / down8 / up-deconv8) compacted in
//    one kernel with ballot-aggregated atomics. Fine list shared by stages 1&5.
//  - Register-tiled GEMM per tap segment, W staged in smem, packed fma.rn.f32x2
//    accumulators, red.v4 scatter (DIRECT store for deconv: unique tap per row).
//  - BN batch-stats folded into scale/shift at gather; smem-reduced stats.
// ---------------------------------------------------------------------------

#define NMAX 200000
#define EPSF 1e-4f
#define TPAIR 128
#define GEMM_GRID 1792

__device__ float g_cat[NMAX * 64];     // skip | upsampled (fine)
__device__ float g_xc [NMAX * 64];     // coarse after down conv
__device__ float g_xc2[NMAX * 64];     // coarse after subconv2
__device__ int2  g_pf[27 * NMAX];      // fine 3^3 pairs
__device__ int2  g_pc[27 * NMAX];      // coarse 3^3 pairs
__device__ int2  g_pd[8 * NMAX];       // down 2^3 pairs
__device__ int2  g_pu[8 * NMAX];       // deconv pairs (by up_k)
__device__ int   g_cnt[70];            // 0..26 fine | 27..53 coarse | 54..61 down | 62..69 up
__device__ int   g_tb_f[28], g_tb_c[28], g_tb_d[9], g_tb_u[9];
__device__ double g_sums[128];
__device__ float g_scale[64];
__device__ float g_shift[64];

// ---------------------------------------------------------------------------
__global__ void prep_kernel() {
    int t = threadIdx.x;
    g_sums[t] = 0.0;
    if (t < 70) g_cnt[t] = 0;
}

// per-channel sum & sumsq; smem reduction, one atomic per channel per block
template <int C>
__global__ void stats_kernel(const float* __restrict__ x, int nrows, int ld) {
    constexpr int G = 256 / C;
    __shared__ double sm[512];
    int c = threadIdx.x % C;
    int g = threadIdx.x / C;
    double s = 0.0, s2 = 0.0;
    for (int r = blockIdx.x * G + g; r < nrows; r += gridDim.x * G) {
        float v = x[(size_t)r * ld + c];
        s += (double)v; s2 += (double)v * (double)v;
    }
    sm[threadIdx.x] = s; sm[256 + threadIdx.x] = s2;
    __syncthreads();
    if (g == 0) {
        #pragma unroll
        for (int j = 1; j < G; j++) { s += sm[j * C + c]; s2 += sm[256 + j * C + c]; }
        atomicAdd(&g_sums[c], s);
        atomicAdd(&g_sums[64 + c], s2);
    }
}

// computes scale/shift for this stage, then zeroes sums for the next stage
__global__ void finalize_kernel(const float* __restrict__ g,
                                const float* __restrict__ b,
                                int C, float inv_n) {
    int c = threadIdx.x;                     // 64 threads
    double s = g_sums[c], s2 = g_sums[64 + c];
    if (c < C) {
        float mu  = (float)(s * inv_n);
        float var = (float)(s2 * inv_n) - mu * mu;
        float inv = rsqrtf(var + EPSF);
        float sc  = g[c] * inv;
        g_scale[c] = sc;
        g_shift[c] = b[c] - mu * sc;
    }
    g_sums[c] = 0.0; g_sums[64 + c] = 0.0;
}

// ---------------------------------------------------------------------------
// One kernel compacts all 70 (out_row, in_row) tap segments.
__global__ void compact_all_kernel(const int* __restrict__ nf,
                                   const int* __restrict__ nc,
                                   const int* __restrict__ dn,
                                   const int* __restrict__ uci,
                                   const int* __restrict__ uk,
                                   int N, int M) {
    int seg = blockIdx.y;
    const int* src = nullptr; int nrows, sent = 0; int2* out; bool dec = false; int kd = 0;
    if (seg < 27)      { src = nf + (size_t)seg * N;        nrows = N; sent = N; out = g_pf + (size_t)seg * NMAX; }
    else if (seg < 54) { src = nc + (size_t)(seg - 27) * M; nrows = M; sent = M; out = g_pc + (size_t)(seg - 27) * NMAX; }
    else if (seg < 62) { src = dn + (size_t)(seg - 54) * M; nrows = M; sent = N; out = g_pd + (size_t)(seg - 54) * NMAX; }
    else               { nrows = N; out = g_pu + (size_t)(seg - 62) * NMAX; dec = true; kd = seg - 62; }
    int* cnt = &g_cnt[seg];
    int lane = threadIdx.x & 31;
    int base = (blockIdx.x * 256 + threadIdx.x) * 4;

    #pragma unroll
    for (int j = 0; j < 4; j++) {
        int r = base + j;
        int idx = 0; bool valid = false;
        if (r < nrows) {
            if (dec) { valid = (__ldg(uk + r) == kd); idx = __ldg(uci + r); }
            else     { idx = __ldg(src + r); valid = idx < sent; }
        }
        unsigned m = __ballot_sync(0xffffffffu, valid);
        if (m) {
            int ldr = __ffs(m) - 1;
            int pos = 0;
            if (lane == ldr) pos = atomicAdd(cnt, __popc(m));
            pos = __shfl_sync(0xffffffffu, pos, ldr);
            if (valid) out[pos + __popc(m & ((1u << lane) - 1))] = make_int2(r, idx);
        }
    }
}

__global__ void plan_all_kernel() {
    int t = threadIdx.x;
    if (t >= 4) return;
    const int off0[5] = {0, 27, 54, 62, 70};
    int* tb = (t == 0) ? g_tb_f : (t == 1) ? g_tb_c : (t == 2) ? g_tb_d : g_tb_u;
    int s = 0;
    for (int k = off0[t]; k < off0[t + 1]; k++) {
        tb[k - off0[t]] = s;
        s += (g_cnt[k] + TPAIR - 1) / TPAIR;
    }
    tb[off0[t + 1] - off0[t]] = s;
}

// ---------------------------------------------------------------------------
__device__ __forceinline__ void red_add_v4(float* a, float x, float y, float z, float w) {
    asm volatile("red.global.add.v4.f32 [%0], {%1,%2,%3,%4};"
                 :: "l"(a), "f"(x), "f"(y), "f"(z), "f"(w) : "memory");
}
__device__ __forceinline__ unsigned long long pack2(float a) {
    unsigned long long r;
    asm("mov.b64 %0, {%1, %1};" : "=l"(r) : "r"(__float_as_uint(a)));
    return r;
}
__device__ __forceinline__ void fma2(unsigned long long& d,
                                     unsigned long long a, unsigned long long b) {
    asm("fma.rn.f32x2 %0, %1, %2, %0;" : "+l"(d) : "l"(a), "l"(b));
}
union U2F { unsigned long long u; float2 f; };

// Tap-segmented gather-GEMM. 256 threads handle TPAIR=128 pairs/tile.
// Thread tile: 4 pairs (ty) x CT couts (tx), couts packed 2-wide (f32x2).
template <int CIN, int COUT, bool DIRECT>
__launch_bounds__(256)
__global__ void tapgemm_kernel(const float* __restrict__ fin, int ld_in,
                               const int2* __restrict__ pairs,
                               const int* __restrict__ cnt,
                               const int* __restrict__ tb, int K,
                               const float* __restrict__ W,
                               float* __restrict__ out, int ld_out) {
    constexpr int CP = CIN + 2;     // padded A stride (conflict-free scalar reads)
    constexpr int CT = COUT / 8;    // couts per thread
    constexpr int C4 = CIN / 4;
    constexpr int CU = CT / 2;      // packed accum width

    __shared__ __align__(16) float Wsm[CIN * COUT];
    __shared__ float Asm[TPAIR * CP];
    __shared__ int   rowsm[TPAIR];
    __shared__ int   idxsm[TPAIR];
    __shared__ float ssm[CIN], bsm[CIN];
    __shared__ int   tbsm[32], cntsm[32];

    int tid = threadIdx.x;
    if (tid < CIN) { ssm[tid] = g_scale[tid]; bsm[tid] = g_shift[tid]; }
    if (tid <= K)  tbsm[tid] = tb[tid];
    if (tid <  K)  cntsm[tid] = cnt[tid];
    __syncthreads();

    int total = tbsm[K];
    int tx = tid & 7;        // cout group
    int ty = tid >> 3;       // pair group (0..31)
    int pa = ty * 4;

    for (int t = blockIdx.x; t < total; t += gridDim.x) {
        int k = 0;
        while (tbsm[k + 1] <= t) k++;
        int t0 = (t - tbsm[k]) * TPAIR;
        int np = min(TPAIR, cntsm[k] - t0);

        // stage W tap + pair chunk
        {
            const float4* Wg = (const float4*)(W + (size_t)k * CIN * COUT);
            for (int i = tid; i < CIN * COUT / 4; i += 256)
                ((float4*)Wsm)[i] = __ldg(&Wg[i]);
            if (tid < TPAIR) {
                if (tid < np) {
                    int2 pr = __ldg(&pairs[(size_t)k * NMAX + t0 + tid]);
                    rowsm[tid] = pr.x; idxsm[tid] = pr.y;
                } else { rowsm[tid] = -1; idxsm[tid] = 0; }
            }
        }
        __syncthreads();

        // gather + BN + ReLU into padded Asm
        for (int i = tid; i < TPAIR * C4; i += 256) {
            int p  = i / C4;
            int c4 = i % C4;
            float4 v = __ldg((const float4*)(fin + (size_t)idxsm[p] * ld_in) + c4);
            int c = c4 * 4;
            float* ap = &Asm[p * CP + c];
            ap[0] = fmaxf(fmaf(v.x, ssm[c + 0], bsm[c + 0]), 0.f);
            ap[1] = fmaxf(fmaf(v.y, ssm[c + 1], bsm[c + 1]), 0.f);
            ap[2] = fmaxf(fmaf(v.z, ssm[c + 2], bsm[c + 2]), 0.f);
            ap[3] = fmaxf(fmaf(v.w, ssm[c + 3], bsm[c + 3]), 0.f);
        }
        __syncthreads();

        // packed register-tiled GEMM
        unsigned long long acc[4][CU];
        #pragma unroll
        for (int i = 0; i < 4; i++)
            #pragma unroll
            for (int j = 0; j < CU; j++) acc[i][j] = 0ull;

        const float* a0p = &Asm[pa * CP];
        #pragma unroll 8
        for (int c = 0; c < CIN; c++) {
            unsigned long long aa0 = pack2(a0p[c]);
            unsigned long long aa1 = pack2(a0p[CP + c]);
            unsigned long long aa2 = pack2(a0p[2 * CP + c]);
            unsigned long long aa3 = pack2(a0p[3 * CP + c]);
            const unsigned long long* wr =
                (const unsigned long long*)&Wsm[c * COUT + tx * CT];
            #pragma unroll
            for (int j = 0; j < CU; j++) {
                unsigned long long w = wr[j];
                fma2(acc[0][j], aa0, w);
                fma2(acc[1][j], aa1, w);
                fma2(acc[2][j], aa2, w);
                fma2(acc[3][j], aa3, w);
            }
        }

        // write back
        #pragma unroll
        for (int i = 0; i < 4; i++) {
            int r = rowsm[pa + i];
            if (r >= 0) {
                float* op = out + (size_t)r * ld_out + tx * CT;
                #pragma unroll
                for (int j2 = 0; j2 < CU / 2; j2++) {
                    U2F u0, u1; u0.u = acc[i][2 * j2]; u1.u = acc[i][2 * j2 + 1];
                    if (DIRECT) {
                        *(float4*)(op + 4 * j2) =
                            make_float4(u0.f.x, u0.f.y, u1.f.x, u1.f.y);
                    } else {
                        red_add_v4(op + 4 * j2, u0.f.x, u0.f.y, u1.f.x, u1.f.y);
                    }
                }
            }
        }
        __syncthreads();
    }
}

// ---------------------------------------------------------------------------
extern "C" void kernel_launch(void* const* d_in, const int* in_sizes, int n_in,
                              void* d_out, int out_size) {
    const float* feat    = (const float*)d_in[0];
    const float* w_sub1  = (const float*)d_in[1];
    const float* w_down  = (const float*)d_in[2];
    const float* w_sub2  = (const float*)d_in[3];
    const float* w_up    = (const float*)d_in[4];
    const float* w_sub3  = (const float*)d_in[5];
    const float* g1 = (const float*)d_in[6];  const float* b1 = (const float*)d_in[7];
    const float* g2 = (const float*)d_in[8];  const float* b2 = (const float*)d_in[9];
    const float* g3 = (const float*)d_in[10]; const float* b3 = (const float*)d_in[11];
    const float* g4 = (const float*)d_in[12]; const float* b4 = (const float*)d_in[13];
    const float* g5 = (const float*)d_in[14]; const float* b5 = (const float*)d_in[15];
    const int* nbr_fine   = (const int*)d_in[16];
    const int* nbr_coarse = (const int*)d_in[17];
    const int* down_idx   = (const int*)d_in[18];
    const int* up_cidx    = (const int*)d_in[19];
    const int* up_k       = (const int*)d_in[20];

    const int N = in_sizes[0] / 32;
    const int M = in_sizes[18] / 8;

    float *cat_ptr, *xc_ptr, *xc2_ptr;
    int *cnt_ptr, *tbf, *tbc, *tbd, *tbu;
    cudaGetSymbolAddress((void**)&cat_ptr, g_cat);
    cudaGetSymbolAddress((void**)&xc_ptr,  g_xc);
    cudaGetSymbolAddress((void**)&xc2_ptr, g_xc2);
    cudaGetSymbolAddress((void**)&cnt_ptr, g_cnt);
    cudaGetSymbolAddress((void**)&tbf, g_tb_f);
    cudaGetSymbolAddress((void**)&tbc, g_tb_c);
    cudaGetSymbolAddress((void**)&tbd, g_tb_d);
    cudaGetSymbolAddress((void**)&tbu, g_tb_u);
    int2 *pf, *pc, *pd, *pu;
    cudaGetSymbolAddress((void**)&pf, g_pf);
    cudaGetSymbolAddress((void**)&pc, g_pc);
    cudaGetSymbolAddress((void**)&pd, g_pd);
    cudaGetSymbolAddress((void**)&pu, g_pu);

    // zero accumulation targets
    cudaMemsetAsync(cat_ptr, 0, (size_t)N * 64 * sizeof(float));
    cudaMemsetAsync(xc_ptr,  0, (size_t)M * 64 * sizeof(float));
    cudaMemsetAsync(xc2_ptr, 0, (size_t)M * 64 * sizeof(float));
    cudaMemsetAsync(d_out,   0, (size_t)out_size * sizeof(float));

    // geometry prep (feature-independent): counters, compaction, tile plan
    prep_kernel<<<1, 128>>>();
    int mx = (N > M ? N : M);
    dim3 cg((mx + 1023) / 1024, 70);
    compact_all_kernel<<<cg, 256>>>(nbr_fine, nbr_coarse, down_idx, up_cidx, up_k, N, M);
    plan_all_kernel<<<1, 32>>>();

    const int SG = 296;

    // stage 1: BN(feat) -> subconv1 (32->32, fine taps) into cat[:,0:32]
    stats_kernel<32><<<SG, 256>>>(feat, N, 32);
    finalize_kernel<<<1, 64>>>(g1, b1, 32, 1.0f / N);
    tapgemm_kernel<32, 32, false><<<GEMM_GRID, 256>>>(
        feat, 32, pf, cnt_ptr + 0, tbf, 27, w_sub1, cat_ptr, 64);

    // stage 2: BN(skip) -> down conv (32->64) into xc
    stats_kernel<32><<<SG, 256>>>(cat_ptr, N, 64);
    finalize_kernel<<<1, 64>>>(g2, b2, 32, 1.0f / N);
    tapgemm_kernel<32, 64, false><<<GEMM_GRID, 256>>>(
        cat_ptr, 64, pd, cnt_ptr + 54, tbd, 8, w_down, xc_ptr, 64);

    // stage 3: BN(xc) -> subconv2 (64->64, coarse taps) into xc2
    stats_kernel<64><<<SG, 256>>>(xc_ptr, M, 64);
    finalize_kernel<<<1, 64>>>(g3, b3, 64, 1.0f / M);
    tapgemm_kernel<64, 64, false><<<GEMM_GRID, 256>>>(
        xc_ptr, 64, pc, cnt_ptr + 27, tbc, 27, w_sub2, xc2_ptr, 64);

    // stage 4: BN(xc2) -> deconv (64->32) direct into cat[:,32:64]
    stats_kernel<64><<<SG, 256>>>(xc2_ptr, M, 64);
    finalize_kernel<<<1, 64>>>(g4, b4, 64, 1.0f / M);
    tapgemm_kernel<64, 32, true><<<GEMM_GRID, 256>>>(
        xc2_ptr, 64, pu, cnt_ptr + 62, tbu, 8, w_up, cat_ptr + 32, 64);

    // stage 5: BN(cat) -> subconv3 (64->32, fine taps) into out
    stats_kernel<64><<<SG, 256>>>(cat_ptr, N, 64);
    finalize_kernel<<<1, 64>>>(g5, b5, 64, 1.0f / N);
    tapgemm_kernel<64, 32, false><<<GEMM_GRID, 256>>>(
        cat_ptr, 64, pf, cnt_ptr + 0, tbf, 27, w_sub3, (float*)d_out, 32);
}

// round 7
// speedup vs baseline: 4.2775x; 1.3669x over previous
#include <cuda_runtime.h>
#include <math.h>

// ---------------------------------------------------------------------------
// Sparse UNet block via tap-compacted dense gather-GEMMs (f32x2-packed FFMA).
//  - All 70 tap segments compacted in one kernel (ballot-aggregated atomics).
//  - Register-tiled GEMM per tap segment, W in smem, fma.rn.f32x2 accumulators,
//    red.v4 scatter (DIRECT store for deconv).
//  - BN batch stats: float4 vectorized, unrolled (MLP=4), smem-reduced,
//    slot-spread double atomics. Folded into scale/shift at gather.
// ---------------------------------------------------------------------------

#define NMAX 200000
#define EPSF 1e-4f
#define TPAIR 128
#define GEMM_GRID 1792
#define STATS_GRID 296
#define NSLOT 8

__device__ float g_buf[(size_t)NMAX * 64 * 3]; // cat | xc | xc2 (one memset)
__device__ int2  g_pf[27 * NMAX];      // fine 3^3 pairs
__device__ int2  g_pc[27 * NMAX];      // coarse 3^3 pairs
__device__ int2  g_pd[8 * NMAX];       // down 2^3 pairs
__device__ int2  g_pu[8 * NMAX];       // deconv pairs (by up_k)
__device__ int   g_cnt[70];            // 0..26 fine | 27..53 coarse | 54..61 down | 62..69 up
__device__ int   g_tb_f[28], g_tb_c[28], g_tb_d[9], g_tb_u[9];
__device__ double g_sums[NSLOT][128];  // slot-spread per-channel sum / sumsq
__device__ float g_scale[64];
__device__ float g_shift[64];

// ---------------------------------------------------------------------------
__global__ void prep_kernel() {
    int t = threadIdx.x;                       // 1024 threads
    ((double*)g_sums)[t] = 0.0;
    if (t < 70) g_cnt[t] = 0;
}

// Vectorized per-channel sum & sumsq. Thread owns 4 channels (float4 lane),
// strides rows with unroll-4 (MLP). fp32 partials -> smem reduce -> slotted
// double atomics.
template <int C>
__global__ void stats_kernel(const float* __restrict__ x, int nrows, int ld) {
    constexpr int TPR = C / 4;        // threads per row
    constexpr int RPB = 256 / TPR;    // rows per block pass
    __shared__ float smS[256 * 4], smQ[256 * 4];

    int tid = threadIdx.x;
    int tr = tid % TPR;               // float4 slot within row
    int rg = tid / TPR;               // row group
    float4 s  = make_float4(0.f, 0.f, 0.f, 0.f);
    float4 q  = make_float4(0.f, 0.f, 0.f, 0.f);

    int stride = gridDim.x * RPB;
    #pragma unroll 4
    for (int r = blockIdx.x * RPB + rg; r < nrows; r += stride) {
        float4 v = __ldg((const float4*)(x + (size_t)r * ld) + tr);
        s.x += v.x; s.y += v.y; s.z += v.z; s.w += v.w;
        q.x = fmaf(v.x, v.x, q.x); q.y = fmaf(v.y, v.y, q.y);
        q.z = fmaf(v.z, v.z, q.z); q.w = fmaf(v.w, v.w, q.w);
    }
    ((float4*)smS)[tid] = s;
    ((float4*)smQ)[tid] = q;
    __syncthreads();

    if (rg == 0) {                     // first TPR threads reduce their channels
        #pragma unroll
        for (int j = 1; j < RPB; j++) {
            float4 a = ((float4*)smS)[j * TPR + tr];
            float4 b = ((float4*)smQ)[j * TPR + tr];
            s.x += a.x; s.y += a.y; s.z += a.z; s.w += a.w;
            q.x += b.x; q.y += b.y; q.z += b.z; q.w += b.w;
        }
        int slot = blockIdx.x & (NSLOT - 1);
        int c = tr * 4;
        atomicAdd(&g_sums[slot][c + 0], (double)s.x);
        atomicAdd(&g_sums[slot][c + 1], (double)s.y);
        atomicAdd(&g_sums[slot][c + 2], (double)s.z);
        atomicAdd(&g_sums[slot][c + 3], (double)s.w);
        atomicAdd(&g_sums[slot][64 + c + 0], (double)q.x);
        atomicAdd(&g_sums[slot][64 + c + 1], (double)q.y);
        atomicAdd(&g_sums[slot][64 + c + 2], (double)q.z);
        atomicAdd(&g_sums[slot][64 + c + 3], (double)q.w);
    }
}

// computes scale/shift for this stage, then zeroes sums for the next stage
__global__ void finalize_kernel(const float* __restrict__ g,
                                const float* __restrict__ b,
                                int C, float inv_n) {
    int c = threadIdx.x;                     // 64 threads
    double s = 0.0, s2 = 0.0;
    #pragma unroll
    for (int j = 0; j < NSLOT; j++) {
        s  += g_sums[j][c];      g_sums[j][c] = 0.0;
        s2 += g_sums[j][64 + c]; g_sums[j][64 + c] = 0.0;
    }
    if (c < C) {
        float mu  = (float)(s * inv_n);
        float var = (float)(s2 * inv_n) - mu * mu;
        float inv = rsqrtf(var + EPSF);
        float sc  = g[c] * inv;
        g_scale[c] = sc;
        g_shift[c] = b[c] - mu * sc;
    }
}

// ---------------------------------------------------------------------------
// One kernel compacts all 70 (out_row, in_row) tap segments.
__global__ void compact_all_kernel(const int* __restrict__ nf,
                                   const int* __restrict__ nc,
                                   const int* __restrict__ dn,
                                   const int* __restrict__ uci,
                                   const int* __restrict__ uk,
                                   int N, int M) {
    int seg = blockIdx.y;
    const int* src = nullptr; int nrows, sent = 0; int2* out; bool dec = false; int kd = 0;
    if (seg < 27)      { src = nf + (size_t)seg * N;        nrows = N; sent = N; out = g_pf + (size_t)seg * NMAX; }
    else if (seg < 54) { src = nc + (size_t)(seg - 27) * M; nrows = M; sent = M; out = g_pc + (size_t)(seg - 27) * NMAX; }
    else if (seg < 62) { src = dn + (size_t)(seg - 54) * M; nrows = M; sent = N; out = g_pd + (size_t)(seg - 54) * NMAX; }
    else               { nrows = N; out = g_pu + (size_t)(seg - 62) * NMAX; dec = true; kd = seg - 62; }
    int* cnt = &g_cnt[seg];
    int lane = threadIdx.x & 31;
    int base = (blockIdx.x * 256 + threadIdx.x) * 4;

    #pragma unroll
    for (int j = 0; j < 4; j++) {
        int r = base + j;
        int idx = 0; bool valid = false;
        if (r < nrows) {
            if (dec) { valid = (__ldg(uk + r) == kd); idx = __ldg(uci + r); }
            else     { idx = __ldg(src + r); valid = idx < sent; }
        }
        unsigned m = __ballot_sync(0xffffffffu, valid);
        if (m) {
            int ldr = __ffs(m) - 1;
            int pos = 0;
            if (lane == ldr) pos = atomicAdd(cnt, __popc(m));
            pos = __shfl_sync(0xffffffffu, pos, ldr);
            if (valid) out[pos + __popc(m & ((1u << lane) - 1))] = make_int2(r, idx);
        }
    }
}

__global__ void plan_all_kernel() {
    int t = threadIdx.x;
    if (t >= 4) return;
    const int off0[5] = {0, 27, 54, 62, 70};
    int* tb = (t == 0) ? g_tb_f : (t == 1) ? g_tb_c : (t == 2) ? g_tb_d : g_tb_u;
    int s = 0;
    for (int k = off0[t]; k < off0[t + 1]; k++) {
        tb[k - off0[t]] = s;
        s += (g_cnt[k] + TPAIR - 1) / TPAIR;
    }
    tb[off0[t + 1] - off0[t]] = s;
}

// ---------------------------------------------------------------------------
__device__ __forceinline__ void red_add_v4(float* a, float x, float y, float z, float w) {
    asm volatile("red.global.add.v4.f32 [%0], {%1,%2,%3,%4};"
                 :: "l"(a), "f"(x), "f"(y), "f"(z), "f"(w) : "memory");
}
__device__ __forceinline__ unsigned long long pack2(float a) {
    unsigned long long r;
    asm("mov.b64 %0, {%1, %1};" : "=l"(r) : "r"(__float_as_uint(a)));
    return r;
}
__device__ __forceinline__ void fma2(unsigned long long& d,
                                     unsigned long long a, unsigned long long b) {
    asm("fma.rn.f32x2 %0, %1, %2, %0;" : "+l"(d) : "l"(a), "l"(b));
}
union U2F { unsigned long long u; float2 f; };

// Tap-segmented gather-GEMM. 256 threads handle TPAIR=128 pairs/tile.
// Thread tile: 4 pairs (ty) x CT couts (tx), couts packed 2-wide (f32x2).
template <int CIN, int COUT, bool DIRECT>
__launch_bounds__(256)
__global__ void tapgemm_kernel(const float* __restrict__ fin, int ld_in,
                               const int2* __restrict__ pairs,
                               const int* __restrict__ cnt,
                               const int* __restrict__ tb, int K,
                               const float* __restrict__ W,
                               float* __restrict__ out, int ld_out) {
    constexpr int CP = CIN + 2;     // padded A stride (conflict-free scalar reads)
    constexpr int CT = COUT / 8;    // couts per thread
    constexpr int C4 = CIN / 4;
    constexpr int CU = CT / 2;      // packed accum width

    __shared__ __align__(16) float Wsm[CIN * COUT];
    __shared__ float Asm[TPAIR * CP];
    __shared__ int   rowsm[TPAIR];
    __shared__ int   idxsm[TPAIR];
    __shared__ float ssm[CIN], bsm[CIN];
    __shared__ int   tbsm[32], cntsm[32];

    int tid = threadIdx.x;
    if (tid < CIN) { ssm[tid] = g_scale[tid]; bsm[tid] = g_shift[tid]; }
    if (tid <= K)  tbsm[tid] = tb[tid];
    if (tid <  K)  cntsm[tid] = cnt[tid];
    __syncthreads();

    int total = tbsm[K];
    int tx = tid & 7;        // cout group
    int ty = tid >> 3;       // pair group (0..31)
    int pa = ty * 4;

    for (int t = blockIdx.x; t < total; t += gridDim.x) {
        int k = 0;
        while (tbsm[k + 1] <= t) k++;
        int t0 = (t - tbsm[k]) * TPAIR;
        int np = min(TPAIR, cntsm[k] - t0);

        // stage W tap + pair chunk
        {
            const float4* Wg = (const float4*)(W + (size_t)k * CIN * COUT);
            for (int i = tid; i < CIN * COUT / 4; i += 256)
                ((float4*)Wsm)[i] = __ldg(&Wg[i]);
            if (tid < TPAIR) {
                if (tid < np) {
                    int2 pr = __ldg(&pairs[(size_t)k * NMAX + t0 + tid]);
                    rowsm[tid] = pr.x; idxsm[tid] = pr.y;
                } else { rowsm[tid] = -1; idxsm[tid] = 0; }
            }
        }
        __syncthreads();

        // gather + BN + ReLU into padded Asm
        for (int i = tid; i < TPAIR * C4; i += 256) {
            int p  = i / C4;
            int c4 = i % C4;
            float4 v = __ldg((const float4*)(fin + (size_t)idxsm[p] * ld_in) + c4);
            int c = c4 * 4;
            float* ap = &Asm[p * CP + c];
            ap[0] = fmaxf(fmaf(v.x, ssm[c + 0], bsm[c + 0]), 0.f);
            ap[1] = fmaxf(fmaf(v.y, ssm[c + 1], bsm[c + 1]), 0.f);
            ap[2] = fmaxf(fmaf(v.z, ssm[c + 2], bsm[c + 2]), 0.f);
            ap[3] = fmaxf(fmaf(v.w, ssm[c + 3], bsm[c + 3]), 0.f);
        }
        __syncthreads();

        // packed register-tiled GEMM
        unsigned long long acc[4][CU];
        #pragma unroll
        for (int i = 0; i < 4; i++)
            #pragma unroll
            for (int j = 0; j < CU; j++) acc[i][j] = 0ull;

        const float* a0p = &Asm[pa * CP];
        #pragma unroll 8
        for (int c = 0; c < CIN; c++) {
            unsigned long long aa0 = pack2(a0p[c]);
            unsigned long long aa1 = pack2(a0p[CP + c]);
            unsigned long long aa2 = pack2(a0p[2 * CP + c]);
            unsigned long long aa3 = pack2(a0p[3 * CP + c]);
            const ulonglong2* wr = (const ulonglong2*)&Wsm[c * COUT + tx * CT];
            #pragma unroll
            for (int j = 0; j < CU / 2; j++) {
                ulonglong2 w2 = wr[j];
                fma2(acc[0][2*j], aa0, w2.x); fma2(acc[0][2*j+1], aa0, w2.y);
                fma2(acc[1][2*j], aa1, w2.x); fma2(acc[1][2*j+1], aa1, w2.y);
                fma2(acc[2][2*j], aa2, w2.x); fma2(acc[2][2*j+1], aa2, w2.y);
                fma2(acc[3][2*j], aa3, w2.x); fma2(acc[3][2*j+1], aa3, w2.y);
            }
        }

        // write back
        #pragma unroll
        for (int i = 0; i < 4; i++) {
            int r = rowsm[pa + i];
            if (r >= 0) {
                float* op = out + (size_t)r * ld_out + tx * CT;
                #pragma unroll
                for (int j2 = 0; j2 < CU / 2; j2++) {
                    U2F u0, u1; u0.u = acc[i][2 * j2]; u1.u = acc[i][2 * j2 + 1];
                    if (DIRECT) {
                        *(float4*)(op + 4 * j2) =
                            make_float4(u0.f.x, u0.f.y, u1.f.x, u1.f.y);
                    } else {
                        red_add_v4(op + 4 * j2, u0.f.x, u0.f.y, u1.f.x, u1.f.y);
                    }
                }
            }
        }
        __syncthreads();
    }
}

// ---------------------------------------------------------------------------
extern "C" void kernel_launch(void* const* d_in, const int* in_sizes, int n_in,
                              void* d_out, int out_size) {
    const float* feat    = (const float*)d_in[0];
    const float* w_sub1  = (const float*)d_in[1];
    const float* w_down  = (const float*)d_in[2];
    const float* w_sub2  = (const float*)d_in[3];
    const float* w_up    = (const float*)d_in[4];
    const float* w_sub3  = (const float*)d_in[5];
    const float* g1 = (const float*)d_in[6];  const float* b1 = (const float*)d_in[7];
    const float* g2 = (const float*)d_in[8];  const float* b2 = (const float*)d_in[9];
    const float* g3 = (const float*)d_in[10]; const float* b3 = (const float*)d_in[11];
    const float* g4 = (const float*)d_in[12]; const float* b4 = (const float*)d_in[13];
    const float* g5 = (const float*)d_in[14]; const float* b5 = (const float*)d_in[15];
    const int* nbr_fine   = (const int*)d_in[16];
    const int* nbr_coarse = (const int*)d_in[17];
    const int* down_idx   = (const int*)d_in[18];
    const int* up_cidx    = (const int*)d_in[19];
    const int* up_k       = (const int*)d_in[20];

    const int N = in_sizes[0] / 32;
    const int M = in_sizes[18] / 8;

    float* buf;
    int *cnt_ptr, *tbf, *tbc, *tbd, *tbu;
    cudaGetSymbolAddress((void**)&buf, g_buf);
    cudaGetSymbolAddress((void**)&cnt_ptr, g_cnt);
    cudaGetSymbolAddress((void**)&tbf, g_tb_f);
    cudaGetSymbolAddress((void**)&tbc, g_tb_c);
    cudaGetSymbolAddress((void**)&tbd, g_tb_d);
    cudaGetSymbolAddress((void**)&tbu, g_tb_u);
    int2 *pf, *pc, *pd, *pu;
    cudaGetSymbolAddress((void**)&pf, g_pf);
    cudaGetSymbolAddress((void**)&pc, g_pc);
    cudaGetSymbolAddress((void**)&pd, g_pd);
    cudaGetSymbolAddress((void**)&pu, g_pu);

    float* cat_ptr = buf;
    float* xc_ptr  = buf + (size_t)NMAX * 64;
    float* xc2_ptr = buf + (size_t)NMAX * 64 * 2;

    // zero accumulation targets (cat/xc/xc2 contiguous -> one memset)
    cudaMemsetAsync(buf, 0, ((size_t)N * 64 +
                             (size_t)(NMAX + M) * 64) * sizeof(float));
    cudaMemsetAsync(d_out, 0, (size_t)out_size * sizeof(float));

    // geometry prep (feature-independent): counters, compaction, tile plan
    prep_kernel<<<1, 1024>>>();
    int mx = (N > M ? N : M);
    dim3 cg((mx + 1023) / 1024, 70);
    compact_all_kernel<<<cg, 256>>>(nbr_fine, nbr_coarse, down_idx, up_cidx, up_k, N, M);
    plan_all_kernel<<<1, 32>>>();

    // stage 1: BN(feat) -> subconv1 (32->32, fine taps) into cat[:,0:32]
    stats_kernel<32><<<STATS_GRID, 256>>>(feat, N, 32);
    finalize_kernel<<<1, 64>>>(g1, b1, 32, 1.0f / N);
    tapgemm_kernel<32, 32, false><<<GEMM_GRID, 256>>>(
        feat, 32, pf, cnt_ptr + 0, tbf, 27, w_sub1, cat_ptr, 64);

    // stage 2: BN(skip) -> down conv (32->64) into xc
    stats_kernel<32><<<STATS_GRID, 256>>>(cat_ptr, N, 64);
    finalize_kernel<<<1, 64>>>(g2, b2, 32, 1.0f / N);
    tapgemm_kernel<32, 64, false><<<GEMM_GRID, 256>>>(
        cat_ptr, 64, pd, cnt_ptr + 54, tbd, 8, w_down, xc_ptr, 64);

    // stage 3: BN(xc) -> subconv2 (64->64, coarse taps) into xc2
    stats_kernel<64><<<STATS_GRID, 256>>>(xc_ptr, M, 64);
    finalize_kernel<<<1, 64>>>(g3, b3, 64, 1.0f / M);
    tapgemm_kernel<64, 64, false><<<GEMM_GRID, 256>>>(
        xc_ptr, 64, pc, cnt_ptr + 27, tbc, 27, w_sub2, xc2_ptr, 64);

    // stage 4: BN(xc2) -> deconv (64->32) direct into cat[:,32:64]
    stats_kernel<64><<<STATS_GRID, 256>>>(xc2_ptr, M, 64);
    finalize_kernel<<<1, 64>>>(g4, b4, 64, 1.0f / M);
    tapgemm_kernel<64, 32, true><<<GEMM_GRID, 256>>>(
        xc2_ptr, 64, pu, cnt_ptr + 62, tbu, 8, w_up, cat_ptr + 32, 64);

    // stage 5: BN(cat) -> subconv3 (64->32, fine taps) into out
    stats_kernel<64><<<STATS_GRID, 256>>>(cat_ptr, N, 64);
    finalize_kernel<<<1, 64>>>(g5, b5, 64, 1.0f / N);
    tapgemm_kernel<64, 32, false><<<GEMM_GRID, 256>>>(
        cat_ptr, 64, pf, cnt_ptr + 0, tbf, 27, w_sub3, (float*)d_out, 32);
}

// round 8
// speedup vs baseline: 4.4469x; 1.0396x over previous
#include <cuda_runtime.h>
#include <math.h>

// ---------------------------------------------------------------------------
// Sparse UNet block via tap-compacted dense gather-GEMMs (f32x2-packed FFMA).
//  - All 70 tap segments compacted in one kernel (ballot atomics); tile plan
//    fused into the compaction kernel via last-block ticket.
//  - BN batch stats: float4 vectorized, occupancy-scaled grid, smem-reduced,
//    slot-spread double atomics; finalize (scale/shift) fused via last-block
//    ticket. Folded into the gather as scale/shift.
//  - Register-tiled GEMM per tap segment, W in smem, fma.rn.f32x2 accumulators,
//    red.v4 scatter (DIRECT store for deconv).
// ---------------------------------------------------------------------------

#define NMAX 200000
#define EPSF 1e-4f
#define TPAIR 128
#define GEMM_GRID 1792
#define STATS_GRID 740
#define NSLOT 8

__device__ float g_buf[(size_t)NMAX * 64 * 3]; // cat | xc | xc2 (one memset)
__device__ int2  g_pf[27 * NMAX];      // fine 3^3 pairs
__device__ int2  g_pc[27 * NMAX];      // coarse 3^3 pairs
__device__ int2  g_pd[8 * NMAX];       // down 2^3 pairs
__device__ int2  g_pu[8 * NMAX];       // deconv pairs (by up_k)
__device__ int   g_cnt[70];            // 0..26 fine | 27..53 coarse | 54..61 down | 62..69 up
__device__ int   g_tb_f[28], g_tb_c[28], g_tb_d[9], g_tb_u[9];
__device__ double g_sums[NSLOT][128];  // slot-spread per-channel sum / sumsq
__device__ float g_scale[64];
__device__ float g_shift[64];
__device__ int   g_stick;              // stats completion ticket
__device__ int   g_ctick;              // compact completion ticket

// ---------------------------------------------------------------------------
__global__ void prep_kernel() {
    int t = threadIdx.x;                       // 1024 threads
    ((double*)g_sums)[t] = 0.0;
    if (t < 70) g_cnt[t] = 0;
    if (t == 0) { g_stick = 0; g_ctick = 0; }
}

// Vectorized per-channel sum & sumsq, with finalize fused into the last block
// to complete (computes scale/shift, zeroes sums, resets ticket).
template <int C>
__global__ void stats_kernel(const float* __restrict__ x, int nrows, int ld,
                             const float* __restrict__ gw,
                             const float* __restrict__ bw, float inv_n) {
    constexpr int TPR = C / 4;        // threads per row
    constexpr int RPB = 256 / TPR;    // rows per block pass
    __shared__ float smS[256 * 4], smQ[256 * 4];
    __shared__ bool lastsm;

    int tid = threadIdx.x;
    int tr = tid % TPR;               // float4 slot within row
    int rg = tid / TPR;               // row group
    float4 s = make_float4(0.f, 0.f, 0.f, 0.f);
    float4 q = make_float4(0.f, 0.f, 0.f, 0.f);

    int stride = gridDim.x * RPB;
    #pragma unroll 4
    for (int r = blockIdx.x * RPB + rg; r < nrows; r += stride) {
        float4 v = __ldg((const float4*)(x + (size_t)r * ld) + tr);
        s.x += v.x; s.y += v.y; s.z += v.z; s.w += v.w;
        q.x = fmaf(v.x, v.x, q.x); q.y = fmaf(v.y, v.y, q.y);
        q.z = fmaf(v.z, v.z, q.z); q.w = fmaf(v.w, v.w, q.w);
    }
    ((float4*)smS)[tid] = s;
    ((float4*)smQ)[tid] = q;
    __syncthreads();

    if (rg == 0) {                     // first TPR threads reduce their channels
        #pragma unroll
        for (int j = 1; j < RPB; j++) {
            float4 a = ((float4*)smS)[j * TPR + tr];
            float4 b = ((float4*)smQ)[j * TPR + tr];
            s.x += a.x; s.y += a.y; s.z += a.z; s.w += a.w;
            q.x += b.x; q.y += b.y; q.z += b.z; q.w += b.w;
        }
        int slot = blockIdx.x & (NSLOT - 1);
        int c = tr * 4;
        atomicAdd(&g_sums[slot][c + 0], (double)s.x);
        atomicAdd(&g_sums[slot][c + 1], (double)s.y);
        atomicAdd(&g_sums[slot][c + 2], (double)s.z);
        atomicAdd(&g_sums[slot][c + 3], (double)s.w);
        atomicAdd(&g_sums[slot][64 + c + 0], (double)q.x);
        atomicAdd(&g_sums[slot][64 + c + 1], (double)q.y);
        atomicAdd(&g_sums[slot][64 + c + 2], (double)q.z);
        atomicAdd(&g_sums[slot][64 + c + 3], (double)q.w);
        __threadfence();               // publish atomics before ticket
    }
    __syncthreads();
    if (tid == 0)
        lastsm = (atomicAdd(&g_stick, 1) == (int)gridDim.x - 1);
    __syncthreads();

    if (lastsm) {                      // fused finalize
        __threadfence();               // acquire all blocks' sums
        int c = tid;                   // channels 0..63
        if (c < 64) {
            double ss = 0.0, s2 = 0.0;
            #pragma unroll
            for (int j = 0; j < NSLOT; j++) {
                ss += g_sums[j][c];      g_sums[j][c] = 0.0;
                s2 += g_sums[j][64 + c]; g_sums[j][64 + c] = 0.0;
            }
            if (c < C) {
                float mu  = (float)(ss * inv_n);
                float var = (float)(s2 * inv_n) - mu * mu;
                float inv = rsqrtf(var + EPSF);
                float sc  = gw[c] * inv;
                g_scale[c] = sc;
                g_shift[c] = bw[c] - mu * sc;
            }
        }
        if (tid == 0) g_stick = 0;
    }
}

// ---------------------------------------------------------------------------
// One kernel compacts all 70 (out_row, in_row) tap segments; the last block to
// finish computes the tile-plan prefix sums (fused plan).
__global__ void compact_all_kernel(const int* __restrict__ nf,
                                   const int* __restrict__ nc,
                                   const int* __restrict__ dn,
                                   const int* __restrict__ uci,
                                   const int* __restrict__ uk,
                                   int N, int M) {
    __shared__ bool lastsm;
    int seg = blockIdx.y;
    const int* src = nullptr; int nrows, sent = 0; int2* out; bool dec = false; int kd = 0;
    if (seg < 27)      { src = nf + (size_t)seg * N;        nrows = N; sent = N; out = g_pf + (size_t)seg * NMAX; }
    else if (seg < 54) { src = nc + (size_t)(seg - 27) * M; nrows = M; sent = M; out = g_pc + (size_t)(seg - 27) * NMAX; }
    else if (seg < 62) { src = dn + (size_t)(seg - 54) * M; nrows = M; sent = N; out = g_pd + (size_t)(seg - 54) * NMAX; }
    else               { nrows = N; out = g_pu + (size_t)(seg - 62) * NMAX; dec = true; kd = seg - 62; }
    int* cnt = &g_cnt[seg];
    int lane = threadIdx.x & 31;
    int base = (blockIdx.x * 256 + threadIdx.x) * 4;

    #pragma unroll
    for (int j = 0; j < 4; j++) {
        int r = base + j;
        int idx = 0; bool valid = false;
        if (r < nrows) {
            if (dec) { valid = (__ldg(uk + r) == kd); idx = __ldg(uci + r); }
            else     { idx = __ldg(src + r); valid = idx < sent; }
        }
        unsigned m = __ballot_sync(0xffffffffu, valid);
        if (m) {
            int ldr = __ffs(m) - 1;
            int pos = 0;
            if (lane == ldr) pos = atomicAdd(cnt, __popc(m));
            pos = __shfl_sync(0xffffffffu, pos, ldr);
            if (valid) out[pos + __popc(m & ((1u << lane) - 1))] = make_int2(r, idx);
        }
    }

    __threadfence();
    __syncthreads();
    if (threadIdx.x == 0) {
        int total = (int)(gridDim.x * gridDim.y);
        lastsm = (atomicAdd(&g_ctick, 1) == total - 1);
    }
    __syncthreads();

    if (lastsm) {                      // fused tile plan
        __threadfence();
        int t = threadIdx.x;
        if (t < 4) {
            const int off0[5] = {0, 27, 54, 62, 70};
            int* tb = (t == 0) ? g_tb_f : (t == 1) ? g_tb_c : (t == 2) ? g_tb_d : g_tb_u;
            int s = 0;
            for (int k = off0[t]; k < off0[t + 1]; k++) {
                tb[k - off0[t]] = s;
                s += (g_cnt[k] + TPAIR - 1) / TPAIR;
            }
            tb[off0[t + 1] - off0[t]] = s;
        }
        if (threadIdx.x == 0) g_ctick = 0;
    }
}

// ---------------------------------------------------------------------------
__device__ __forceinline__ void red_add_v4(float* a, float x, float y, float z, float w) {
    asm volatile("red.global.add.v4.f32 [%0], {%1,%2,%3,%4};"
                 :: "l"(a), "f"(x), "f"(y), "f"(z), "f"(w) : "memory");
}
__device__ __forceinline__ unsigned long long pack2(float a) {
    unsigned long long r;
    asm("mov.b64 %0, {%1, %1};" : "=l"(r) : "r"(__float_as_uint(a)));
    return r;
}
__device__ __forceinline__ void fma2(unsigned long long& d,
                                     unsigned long long a, unsigned long long b) {
    asm("fma.rn.f32x2 %0, %1, %2, %0;" : "+l"(d) : "l"(a), "l"(b));
}
union U2F { unsigned long long u; float2 f; };

// Tap-segmented gather-GEMM. 256 threads handle TPAIR=128 pairs/tile.
// Thread tile: 4 pairs (ty) x CT couts (tx), couts packed 2-wide (f32x2).
template <int CIN, int COUT, bool DIRECT>
__launch_bounds__(256)
__global__ void tapgemm_kernel(const float* __restrict__ fin, int ld_in,
                               const int2* __restrict__ pairs,
                               const int* __restrict__ cnt,
                               const int* __restrict__ tb, int K,
                               const float* __restrict__ W,
                               float* __restrict__ out, int ld_out) {
    constexpr int CP = CIN + 2;     // padded A stride (conflict-free scalar reads)
    constexpr int CT = COUT / 8;    // couts per thread
    constexpr int C4 = CIN / 4;
    constexpr int CU = CT / 2;      // packed accum width

    __shared__ __align__(16) float Wsm[CIN * COUT];
    __shared__ float Asm[TPAIR * CP];
    __shared__ int   rowsm[TPAIR];
    __shared__ int   idxsm[TPAIR];
    __shared__ float ssm[CIN], bsm[CIN];
    __shared__ int   tbsm[32], cntsm[32];

    int tid = threadIdx.x;
    if (tid < CIN) { ssm[tid] = g_scale[tid]; bsm[tid] = g_shift[tid]; }
    if (tid <= K)  tbsm[tid] = tb[tid];
    if (tid <  K)  cntsm[tid] = cnt[tid];
    __syncthreads();

    int total = tbsm[K];
    int tx = tid & 7;        // cout group
    int ty = tid >> 3;       // pair group (0..31)
    int pa = ty * 4;

    for (int t = blockIdx.x; t < total; t += gridDim.x) {
        int k = 0;
        while (tbsm[k + 1] <= t) k++;
        int t0 = (t - tbsm[k]) * TPAIR;
        int np = min(TPAIR, cntsm[k] - t0);

        // stage W tap + pair chunk
        {
            const float4* Wg = (const float4*)(W + (size_t)k * CIN * COUT);
            for (int i = tid; i < CIN * COUT / 4; i += 256)
                ((float4*)Wsm)[i] = __ldg(&Wg[i]);
            if (tid < TPAIR) {
                if (tid < np) {
                    int2 pr = __ldg(&pairs[(size_t)k * NMAX + t0 + tid]);
                    rowsm[tid] = pr.x; idxsm[tid] = pr.y;
                } else { rowsm[tid] = -1; idxsm[tid] = 0; }
            }
        }
        __syncthreads();

        // gather + BN + ReLU into padded Asm
        for (int i = tid; i < TPAIR * C4; i += 256) {
            int p  = i / C4;
            int c4 = i % C4;
            float4 v = __ldg((const float4*)(fin + (size_t)idxsm[p] * ld_in) + c4);
            int c = c4 * 4;
            float* ap = &Asm[p * CP + c];
            ap[0] = fmaxf(fmaf(v.x, ssm[c + 0], bsm[c + 0]), 0.f);
            ap[1] = fmaxf(fmaf(v.y, ssm[c + 1], bsm[c + 1]), 0.f);
            ap[2] = fmaxf(fmaf(v.z, ssm[c + 2], bsm[c + 2]), 0.f);
            ap[3] = fmaxf(fmaf(v.w, ssm[c + 3], bsm[c + 3]), 0.f);
        }
        __syncthreads();

        // packed register-tiled GEMM
        unsigned long long acc[4][CU];
        #pragma unroll
        for (int i = 0; i < 4; i++)
            #pragma unroll
            for (int j = 0; j < CU; j++) acc[i][j] = 0ull;

        const float* a0p = &Asm[pa * CP];
        #pragma unroll 8
        for (int c = 0; c < CIN; c++) {
            unsigned long long aa0 = pack2(a0p[c]);
            unsigned long long aa1 = pack2(a0p[CP + c]);
            unsigned long long aa2 = pack2(a0p[2 * CP + c]);
            unsigned long long aa3 = pack2(a0p[3 * CP + c]);
            const ulonglong2* wr = (const ulonglong2*)&Wsm[c * COUT + tx * CT];
            #pragma unroll
            for (int j = 0; j < CU / 2; j++) {
                ulonglong2 w2 = wr[j];
                fma2(acc[0][2*j], aa0, w2.x); fma2(acc[0][2*j+1], aa0, w2.y);
                fma2(acc[1][2*j], aa1, w2.x); fma2(acc[1][2*j+1], aa1, w2.y);
                fma2(acc[2][2*j], aa2, w2.x); fma2(acc[2][2*j+1], aa2, w2.y);
                fma2(acc[3][2*j], aa3, w2.x); fma2(acc[3][2*j+1], aa3, w2.y);
            }
        }

        // write back
        #pragma unroll
        for (int i = 0; i < 4; i++) {
            int r = rowsm[pa + i];
            if (r >= 0) {
                float* op = out + (size_t)r * ld_out + tx * CT;
                #pragma unroll
                for (int j2 = 0; j2 < CU / 2; j2++) {
                    U2F u0, u1; u0.u = acc[i][2 * j2]; u1.u = acc[i][2 * j2 + 1];
                    if (DIRECT) {
                        *(float4*)(op + 4 * j2) =
                            make_float4(u0.f.x, u0.f.y, u1.f.x, u1.f.y);
                    } else {
                        red_add_v4(op + 4 * j2, u0.f.x, u0.f.y, u1.f.x, u1.f.y);
                    }
                }
            }
        }
        __syncthreads();
    }
}

// ---------------------------------------------------------------------------
extern "C" void kernel_launch(void* const* d_in, const int* in_sizes, int n_in,
                              void* d_out, int out_size) {
    const float* feat    = (const float*)d_in[0];
    const float* w_sub1  = (const float*)d_in[1];
    const float* w_down  = (const float*)d_in[2];
    const float* w_sub2  = (const float*)d_in[3];
    const float* w_up    = (const float*)d_in[4];
    const float* w_sub3  = (const float*)d_in[5];
    const float* g1 = (const float*)d_in[6];  const float* b1 = (const float*)d_in[7];
    const float* g2 = (const float*)d_in[8];  const float* b2 = (const float*)d_in[9];
    const float* g3 = (const float*)d_in[10]; const float* b3 = (const float*)d_in[11];
    const float* g4 = (const float*)d_in[12]; const float* b4 = (const float*)d_in[13];
    const float* g5 = (const float*)d_in[14]; const float* b5 = (const float*)d_in[15];
    const int* nbr_fine   = (const int*)d_in[16];
    const int* nbr_coarse = (const int*)d_in[17];
    const int* down_idx   = (const int*)d_in[18];
    const int* up_cidx    = (const int*)d_in[19];
    const int* up_k       = (const int*)d_in[20];

    const int N = in_sizes[0] / 32;
    const int M = in_sizes[18] / 8;

    float* buf;
    int *cnt_ptr, *tbf, *tbc, *tbd, *tbu;
    cudaGetSymbolAddress((void**)&buf, g_buf);
    cudaGetSymbolAddress((void**)&cnt_ptr, g_cnt);
    cudaGetSymbolAddress((void**)&tbf, g_tb_f);
    cudaGetSymbolAddress((void**)&tbc, g_tb_c);
    cudaGetSymbolAddress((void**)&tbd, g_tb_d);
    cudaGetSymbolAddress((void**)&tbu, g_tb_u);
    int2 *pf, *pc, *pd, *pu;
    cudaGetSymbolAddress((void**)&pf, g_pf);
    cudaGetSymbolAddress((void**)&pc, g_pc);
    cudaGetSymbolAddress((void**)&pd, g_pd);
    cudaGetSymbolAddress((void**)&pu, g_pu);

    float* cat_ptr = buf;
    float* xc_ptr  = buf + (size_t)NMAX * 64;
    float* xc2_ptr = buf + (size_t)NMAX * 64 * 2;

    // zero accumulation targets (cat/xc/xc2 contiguous -> one memset)
    cudaMemsetAsync(buf, 0, ((size_t)N * 64 +
                             (size_t)(NMAX + M) * 64) * sizeof(float));
    cudaMemsetAsync(d_out, 0, (size_t)out_size * sizeof(float));

    // geometry prep (feature-independent): counters, compaction + fused plan
    prep_kernel<<<1, 1024>>>();
    int mx = (N > M ? N : M);
    dim3 cg((mx + 1023) / 1024, 70);
    compact_all_kernel<<<cg, 256>>>(nbr_fine, nbr_coarse, down_idx, up_cidx, up_k, N, M);

    // stage 1: BN(feat) -> subconv1 (32->32, fine taps) into cat[:,0:32]
    stats_kernel<32><<<STATS_GRID, 256>>>(feat, N, 32, g1, b1, 1.0f / N);
    tapgemm_kernel<32, 32, false><<<GEMM_GRID, 256>>>(
        feat, 32, pf, cnt_ptr + 0, tbf, 27, w_sub1, cat_ptr, 64);

    // stage 2: BN(skip) -> down conv (32->64) into xc
    stats_kernel<32><<<STATS_GRID, 256>>>(cat_ptr, N, 64, g2, b2, 1.0f / N);
    tapgemm_kernel<32, 64, false><<<GEMM_GRID, 256>>>(
        cat_ptr, 64, pd, cnt_ptr + 54, tbd, 8, w_down, xc_ptr, 64);

    // stage 3: BN(xc) -> subconv2 (64->64, coarse taps) into xc2
    stats_kernel<64><<<STATS_GRID, 256>>>(xc_ptr, M, 64, g3, b3, 1.0f / M);
    tapgemm_kernel<64, 64, false><<<GEMM_GRID, 256>>>(
        xc_ptr, 64, pc, cnt_ptr + 27, tbc, 27, w_sub2, xc2_ptr, 64);

    // stage 4: BN(xc2) -> deconv (64->32) direct into cat[:,32:64]
    stats_kernel<64><<<STATS_GRID, 256>>>(xc2_ptr, M, 64, g4, b4, 1.0f / M);
    tapgemm_kernel<64, 32, true><<<GEMM_GRID, 256>>>(
        xc2_ptr, 64, pu, cnt_ptr + 62, tbu, 8, w_up, cat_ptr + 32, 64);

    // stage 5: BN(cat) -> subconv3 (64->32, fine taps) into out
    stats_kernel<64><<<STATS_GRID, 256>>>(cat_ptr, N, 64, g5, b5, 1.0f / N);
    tapgemm_kernel<64, 32, false><<<GEMM_GRID, 256>>>(
        cat_ptr, 64, pf, cnt_ptr + 0, tbf, 27, w_sub3, (float*)d_out, 32);
}